// round 2
// baseline (speedup 1.0000x reference)
#include <cuda_runtime.h>
#include <cuda_bf16.h>

// Problem constants (fixed by setup_inputs)
#define KC   8      // mixture components
#define DIM  512    // obs dim
#define HID  512    // hidden
#define AC   1024   // actions
#define SQ   64     // sequences
#define TT   128    // timesteps
#define BB   8192   // SQ*TT

// ---------------- device scratch (static allocation is allowed) -------------
__device__ float g_obs_tf[BB * DIM];                    //  16 MB (tf32 bits)
__device__ float g_W1_tf[KC * DIM * HID];               //  16 MB
__device__ float g_W2_tf[KC * HID * AC];                //  32 MB
__device__ float g_h[(size_t)KC * BB * HID];            // 128 MB (tf32 bits)
__device__ float g_logits[(size_t)KC * BB * AC];        // 256 MB
__device__ float g_lse[KC * BB];
__device__ float g_alp[KC * BB];
__device__ float g_mix[KC * BB];
__device__ int   g_act[BB];

__device__ __forceinline__ float f2tf32(float x) {
    float r;
    asm("cvt.rna.tf32.f32 %0, %1;" : "=f"(r) : "f"(x));
    return r;
}

// ---------------- fp32 -> tf32 conversion -----------------------------------
__global__ void convert_kernel(const float* __restrict__ obs,
                               const float* __restrict__ W1,
                               const float* __restrict__ W2) {
    int i = blockIdx.x * blockDim.x + threadIdx.x;
    const int n_obs = BB * DIM;        // 4M
    const int n_w1  = KC * DIM * HID;  // 2M
    const int n_w2  = KC * HID * AC;   // 4M
    if (i < n_obs) { g_obs_tf[i] = f2tf32(obs[i]); return; }
    int j = i - n_obs;
    if (j < n_w1)  { g_W1_tf[j] = f2tf32(W1[j]); return; }
    int l = j - n_w1;
    if (l < n_w2)  { g_W2_tf[l] = f2tf32(W2[l]); }
}

// ---------------- actions: detect int32 vs int64, normalize to int32 --------
__global__ void prep_actions_kernel(const void* __restrict__ act) {
    const unsigned long long* p64 = (const unsigned long long*)act;
    int bad = 0;
    for (int i = threadIdx.x; i < BB / 2; i += blockDim.x)
        if (p64[i] > 0xFFFFFFFFull) bad = 1;          // only possible if int32 data
    int is32 = __syncthreads_or(bad);
    if (is32) {
        const int* p32 = (const int*)act;
        for (int i = threadIdx.x; i < BB; i += blockDim.x) g_act[i] = p32[i];
    } else {
        const long long* pl = (const long long*)act;
        for (int i = threadIdx.x; i < BB; i += blockDim.x) g_act[i] = (int)pl[i];
    }
}

// ---------------- tf32 mma.sync m16n8k8 helper ------------------------------
__device__ __forceinline__ void mma1688(float* c, const unsigned* a, const unsigned* b) {
    asm volatile(
        "mma.sync.aligned.m16n8k8.row.col.f32.tf32.tf32.f32 "
        "{%0,%1,%2,%3}, {%4,%5,%6,%7}, {%8,%9}, {%0,%1,%2,%3};\n"
        : "+f"(c[0]), "+f"(c[1]), "+f"(c[2]), "+f"(c[3])
        : "r"(a[0]), "r"(a[1]), "r"(a[2]), "r"(a[3]), "r"(b[0]), "r"(b[1]));
}

// ---------------- GEMM: C[M=8192, NT] = A[M,512] * B[512,NT] (+bias, relu?) --
// grid: (NT/128, 64, KC), block 256 threads = 8 warps (2m x 4n), warp tile 64x32
// K-tile = 16 (two m16n8k8 steps), double-buffered SMEM.
template <int NT, bool IS_G1>
__global__ void __launch_bounds__(256) gemm_kernel(const float* __restrict__ bias_all) {
    __shared__ float As[2][128][20];   // 16 K-cols + 4 pad  (bank: 4r+c distinct)
    __shared__ float Bs[2][16][136];   // 128 N-cols + 8 pad (bank: 8k+col distinct)

    const int kcomp = blockIdx.z;
    const int bm = blockIdx.y, bn = blockIdx.x;
    const int tid = threadIdx.x;
    const int warp = tid >> 5, lane = tid & 31;
    const int wm = (warp >> 2) * 64;   // 0 or 64
    const int wn = (warp & 3) * 32;    // 0,32,64,96

    const float* Ag = IS_G1 ? g_obs_tf : (g_h + (size_t)kcomp * BB * HID);
    const float* Bg = IS_G1 ? (g_W1_tf + (size_t)kcomp * DIM * HID)
                            : (g_W2_tf + (size_t)kcomp * HID * AC);
    const float* bias = bias_all + (size_t)kcomp * NT;

    const int base_m = bm * 128;
    const int base_n = bn * 128;

    float acc[4][4][4];
#pragma unroll
    for (int i = 0; i < 4; i++)
#pragma unroll
        for (int j = 0; j < 4; j++)
#pragma unroll
            for (int l = 0; l < 4; l++) acc[i][j][l] = 0.f;

    // global->smem mapping: A tile 128x16 fp32 (512 float4), B tile 16x128 (512 float4)
    const int ar0 = tid >> 2;          // rows 0..63 (+64)
    const int ac0 = (tid & 3) * 4;     // float4 col
    const int br0 = tid >> 5;          // rows 0..7 (+8)
    const int bc0 = (tid & 31) * 4;

    uint4 ra0, ra1, rb0, rb1;

#define LOAD_TILES(kt)                                                                   \
    do {                                                                                 \
        ra0 = *(const uint4*)(Ag + (size_t)(base_m + ar0) * 512 + (kt) * 16 + ac0);      \
        ra1 = *(const uint4*)(Ag + (size_t)(base_m + 64 + ar0) * 512 + (kt) * 16 + ac0); \
        rb0 = *(const uint4*)(Bg + (size_t)((kt) * 16 + br0) * NT + base_n + bc0);       \
        rb1 = *(const uint4*)(Bg + (size_t)((kt) * 16 + 8 + br0) * NT + base_n + bc0);   \
    } while (0)

#define STORE_TILES(buf)                                                                 \
    do {                                                                                 \
        *(uint4*)&As[buf][ar0][ac0]      = ra0;                                          \
        *(uint4*)&As[buf][64 + ar0][ac0] = ra1;                                          \
        *(uint4*)&Bs[buf][br0][bc0]      = rb0;                                          \
        *(uint4*)&Bs[buf][8 + br0][bc0]  = rb1;                                          \
    } while (0)

    LOAD_TILES(0);
    STORE_TILES(0);
    __syncthreads();

    for (int kt = 0; kt < 32; ++kt) {
        const int cur = kt & 1;
        if (kt < 31) LOAD_TILES(kt + 1);

#pragma unroll
        for (int k8 = 0; k8 < 2; k8++) {
            const int kb = k8 * 8;
            unsigned a[4][4];
#pragma unroll
            for (int mf = 0; mf < 4; mf++) {
                const int r0 = wm + mf * 16 + (lane >> 2);
                const int cc = kb + (lane & 3);
                a[mf][0] = __float_as_uint(As[cur][r0][cc]);
                a[mf][1] = __float_as_uint(As[cur][r0 + 8][cc]);
                a[mf][2] = __float_as_uint(As[cur][r0][cc + 4]);
                a[mf][3] = __float_as_uint(As[cur][r0 + 8][cc + 4]);
            }
            unsigned b[4][2];
#pragma unroll
            for (int nf = 0; nf < 4; nf++) {
                const int col = wn + nf * 8 + (lane >> 2);
                const int r0 = kb + (lane & 3);
                b[nf][0] = __float_as_uint(Bs[cur][r0][col]);
                b[nf][1] = __float_as_uint(Bs[cur][r0 + 4][col]);
            }
#pragma unroll
            for (int mf = 0; mf < 4; mf++)
#pragma unroll
                for (int nf = 0; nf < 4; nf++) mma1688(acc[mf][nf], a[mf], b[nf]);
        }

        if (kt < 31) STORE_TILES(cur ^ 1);
        __syncthreads();
    }
#undef LOAD_TILES
#undef STORE_TILES

    // epilogue
#pragma unroll
    for (int mf = 0; mf < 4; mf++) {
        const int row = base_m + wm + mf * 16 + (lane >> 2);
#pragma unroll
        for (int nf = 0; nf < 4; nf++) {
            const int col = base_n + wn + nf * 8 + (lane & 3) * 2;
            const float bv0 = bias[col], bv1 = bias[col + 1];
            if (IS_G1) {
                float* outp = g_h + (size_t)kcomp * BB * HID;
                float2 p0, p1;
                p0.x = f2tf32(fmaxf(acc[mf][nf][0] + bv0, 0.f));
                p0.y = f2tf32(fmaxf(acc[mf][nf][1] + bv1, 0.f));
                p1.x = f2tf32(fmaxf(acc[mf][nf][2] + bv0, 0.f));
                p1.y = f2tf32(fmaxf(acc[mf][nf][3] + bv1, 0.f));
                *(float2*)(outp + (size_t)row * HID + col) = p0;
                *(float2*)(outp + (size_t)(row + 8) * HID + col) = p1;
            } else {
                float* outp = g_logits + (size_t)kcomp * BB * AC;
                float2 p0, p1;
                p0.x = acc[mf][nf][0] + bv0;
                p0.y = acc[mf][nf][1] + bv1;
                p1.x = acc[mf][nf][2] + bv0;
                p1.y = acc[mf][nf][3] + bv1;
                *(float2*)(outp + (size_t)row * AC + col) = p0;
                *(float2*)(outp + (size_t)(row + 8) * AC + col) = p1;
            }
        }
    }
}

// ---------------- logsumexp over A + action-logprob gather ------------------
// one warp per (k,b) row of 1024 floats; grid = KC*BB/8 blocks of 256
__global__ void __launch_bounds__(256) lse_kernel() {
    const int warp = threadIdx.x >> 5, lane = threadIdx.x & 31;
    const int r = blockIdx.x * 8 + warp;           // r = k*BB + b
    const float* row = g_logits + (size_t)r * AC;
    const float4* r4 = (const float4*)row;

    float4 v[8];
    float mx = -1e30f;
#pragma unroll
    for (int i = 0; i < 8; i++) {
        v[i] = r4[lane + i * 32];
        mx = fmaxf(mx, fmaxf(fmaxf(v[i].x, v[i].y), fmaxf(v[i].z, v[i].w)));
    }
#pragma unroll
    for (int o = 16; o; o >>= 1) mx = fmaxf(mx, __shfl_xor_sync(0xFFFFFFFFu, mx, o));

    float s = 0.f;
#pragma unroll
    for (int i = 0; i < 8; i++) {
        s += expf(v[i].x - mx) + expf(v[i].y - mx) + expf(v[i].z - mx) + expf(v[i].w - mx);
    }
#pragma unroll
    for (int o = 16; o; o >>= 1) s += __shfl_xor_sync(0xFFFFFFFFu, s, o);

    if (lane == 0) {
        const float lse = mx + logf(s);
        const int b = r & (BB - 1);
        const int a = g_act[b];
        g_alp[r] = row[a] - lse;
        g_lse[r] = lse;
    }
}

// ---------------- per-sequence mixture recursion ----------------------------
// one 32-thread block per sequence; lanes 0..7 carry components
__global__ void mix_kernel(const float* __restrict__ prior_all, float* __restrict__ out) {
    const int s = blockIdx.x;
    const int lane = threadIdx.x;
    __shared__ float sm_alp[TT * KC];

    for (int i = lane; i < TT * KC; i += 32) {
        const int t = i >> 3, k = i & 7;
        sm_alp[i] = g_alp[k * BB + s * TT + t];
    }
    __syncthreads();

    if (lane < 8) {
        const int k = lane;
        const float prior = prior_all[s * KC + k];
        float cum = 0.f;
        for (int t = 0; t < TT; t++) {
            const float m = prior + cum;
            float mx = m;
#pragma unroll
            for (int o = 4; o; o >>= 1) mx = fmaxf(mx, __shfl_xor_sync(0xFFu, mx, o));
            float se = expf(m - mx);
#pragma unroll
            for (int o = 4; o; o >>= 1) se += __shfl_xor_sync(0xFFu, se, o);
            g_mix[k * BB + s * TT + t] = m - (mx + logf(se));
            cum += sm_alp[t * 8 + k];
        }
        // final mixture logprobs
        const float m = prior + cum;
        float mx = m;
#pragma unroll
        for (int o = 4; o; o >>= 1) mx = fmaxf(mx, __shfl_xor_sync(0xFFu, mx, o));
        float se = expf(m - mx);
#pragma unroll
        for (int o = 4; o; o >>= 1) se += __shfl_xor_sync(0xFFu, se, o);
        out[(size_t)BB * AC + s * KC + k] = m - (mx + logf(se));
    }
}

// ---------------- final combine: logsumexp over K ---------------------------
// one block per b; 256 threads x 4 actions each
__global__ void __launch_bounds__(256) combine_kernel(float* __restrict__ out) {
    const int b = blockIdx.x;
    __shared__ float off[KC];
    if (threadIdx.x < KC) {
        const int k = threadIdx.x;
        off[k] = g_mix[k * BB + b] - g_lse[k * BB + b];
    }
    __syncthreads();

    float o[KC];
#pragma unroll
    for (int k = 0; k < KC; k++) o[k] = off[k];

#pragma unroll
    for (int i = 0; i < 4; i++) {
        const int a = threadIdx.x + i * 256;
        float v[KC];
#pragma unroll
        for (int k = 0; k < KC; k++)
            v[k] = g_logits[((size_t)k * BB + b) * AC + a] + o[k];
        float mx = v[0];
#pragma unroll
        for (int k = 1; k < KC; k++) mx = fmaxf(mx, v[k]);
        float s = 0.f;
#pragma unroll
        for (int k = 0; k < KC; k++) s += expf(v[k] - mx);
        out[(size_t)b * AC + a] = mx + logf(s);
    }
}

// ---------------- launcher ---------------------------------------------------
extern "C" void kernel_launch(void* const* d_in, const int* in_sizes, int n_in,
                              void* d_out, int out_size) {
    const float* obs     = (const float*)d_in[0];
    const void*  actions = d_in[1];
    const float* prior   = (const float*)d_in[2];
    const float* W1      = (const float*)d_in[3];
    const float* b1      = (const float*)d_in[4];
    const float* W2      = (const float*)d_in[5];
    const float* b2      = (const float*)d_in[6];
    float* out = (float*)d_out;

    const int n_conv = BB * DIM + KC * DIM * HID + KC * HID * AC;
    convert_kernel<<<(n_conv + 255) / 256, 256>>>(obs, W1, W2);
    prep_actions_kernel<<<1, 1024>>>(actions);

    gemm_kernel<HID, true><<<dim3(HID / 128, BB / 128, KC), 256>>>(b1);
    gemm_kernel<AC, false><<<dim3(AC / 128, BB / 128, KC), 256>>>(b2);

    lse_kernel<<<KC * BB / 8, 256>>>();
    mix_kernel<<<SQ, 32>>>(prior, out);
    combine_kernel<<<BB, 256>>>(out);
}

// round 4
// speedup vs baseline: 1.0475x; 1.0475x over previous
#include <cuda_runtime.h>
#include <cstdint>

// Problem constants (fixed by setup_inputs)
#define KC   8
#define DIM  512
#define HID  512
#define AC   1024
#define SQ   64
#define TT   128
#define BB   8192

// ---------------- device scratch --------------------------------------------
__device__ float g_obs_tf[BB * DIM];                    //  16 MB (tf32-rounded)
__device__ float g_W1_tf[KC * DIM * HID];               //  16 MB
__device__ float g_W2_tf[KC * HID * AC];                //  32 MB
__device__ float g_h[(size_t)KC * BB * HID];            // 128 MB (tf32-rounded)
__device__ float g_logits[(size_t)KC * BB * AC];        // 256 MB
__device__ float g_pmax[KC * 32 * BB];                  //   8 MB
__device__ float g_psum[KC * 32 * BB];                  //   8 MB
__device__ float g_lse[KC * BB];
__device__ float g_alp[KC * BB];
__device__ float g_mix[KC * BB];
__device__ int   g_act[BB];

__device__ __forceinline__ float f2tf32(float x) {
    float r;
    asm("cvt.rna.tf32.f32 %0, %1;" : "=f"(r) : "f"(x));
    return r;
}

// ---------------- fp32 -> tf32 pre-rounding ---------------------------------
__global__ void convert_kernel(const float* __restrict__ obs,
                               const float* __restrict__ W1,
                               const float* __restrict__ W2) {
    int i = blockIdx.x * blockDim.x + threadIdx.x;
    const int n_obs = BB * DIM;
    const int n_w1  = KC * DIM * HID;
    const int n_w2  = KC * HID * AC;
    if (i < n_obs) { g_obs_tf[i] = f2tf32(obs[i]); return; }
    int j = i - n_obs;
    if (j < n_w1)  { g_W1_tf[j] = f2tf32(W1[j]); return; }
    int l = j - n_w1;
    if (l < n_w2)  { g_W2_tf[l] = f2tf32(W2[l]); }
}

// ---------------- actions: detect int32 vs int64, normalize to int32 --------
__global__ void prep_actions_kernel(const void* __restrict__ act) {
    const unsigned long long* p64 = (const unsigned long long*)act;
    int bad = 0;
    for (int i = threadIdx.x; i < BB / 2; i += blockDim.x)
        if (p64[i] > 0xFFFFFFFFull) bad = 1;
    int is32 = __syncthreads_or(bad);
    if (is32) {
        const int* p32 = (const int*)act;
        for (int i = threadIdx.x; i < BB; i += blockDim.x) g_act[i] = p32[i];
    } else {
        const long long* pl = (const long long*)act;
        for (int i = threadIdx.x; i < BB; i += blockDim.x) g_act[i] = (int)pl[i];
    }
}

// ---------------- tf32 mma.sync m16n8k8 -------------------------------------
__device__ __forceinline__ void mma1688(float* c, const unsigned* a, const unsigned* b) {
    asm volatile(
        "mma.sync.aligned.m16n8k8.row.col.f32.tf32.tf32.f32 "
        "{%0,%1,%2,%3}, {%4,%5,%6,%7}, {%8,%9}, {%0,%1,%2,%3};\n"
        : "+f"(c[0]), "+f"(c[1]), "+f"(c[2]), "+f"(c[3])
        : "r"(a[0]), "r"(a[1]), "r"(a[2]), "r"(a[3]), "r"(b[0]), "r"(b[1]));
}

#define CPASYNC16(dst, src) \
    asm volatile("cp.async.ca.shared.global [%0], [%1], 16;" :: "r"(dst), "l"(src))
#define CP_COMMIT() asm volatile("cp.async.commit_group;" ::: "memory")

// ---------------- GEMM: C[8192, NT] = A[8192,512] * B[512,NT] ---------------
// CTA tile 128x128, 256 thr = 8 warps (2m x 4n), warp 64x32.
// K-tile 32, 16 steps, 3-stage cp.async pipeline.
#define NSTAGE   3
#define KSTEPS   16
#define A_STRIDE 36
#define B_STRIDE 136
#define A_STAGE  (128 * A_STRIDE)                  // floats
#define B_STAGE  (32 * B_STRIDE)
#define STAGE_FLOATS (A_STAGE + B_STAGE)
#define SMEM_BYTES (NSTAGE * STAGE_FLOATS * 4)     // 107,520 B

template <int NT>
__device__ __forceinline__ void load_stage(int s, int tid, float* sm,
                                           uint32_t smem_u32,
                                           const float* Ag, const float* Bg,
                                           int base_m, int base_n) {
    const int buf = s % NSTAGE;
    const uint32_t abase = smem_u32 + buf * STAGE_FLOATS * 4;
    const uint32_t bbase = abase + A_STAGE * 4;
    const int kofs = s * 32;
#pragma unroll
    for (int i = 0; i < 4; i++) {
        const int idx = tid + 256 * i;               // 0..1023
        const int m  = idx >> 3, kq = (idx & 7) * 4; // A: 128 x 32
        CPASYNC16(abase + (m * A_STRIDE + kq) * 4,
                  Ag + (size_t)(base_m + m) * 512 + kofs + kq);
        const int kr = idx >> 5, nq = (idx & 31) * 4; // B: 32 x 128
        CPASYNC16(bbase + (kr * B_STRIDE + nq) * 4,
                  Bg + (size_t)(kofs + kr) * NT + base_n + nq);
    }
    CP_COMMIT();
}

template <int NT, bool IS_G1>
__global__ void __launch_bounds__(256, 2) gemm_tc(const float* __restrict__ bias_all) {
    extern __shared__ float sm[];
    const uint32_t smem_u32 = (uint32_t)__cvta_generic_to_shared(sm);
    const int tid = threadIdx.x, wid = tid >> 5, lane = tid & 31;
    const int kcomp = blockIdx.z, bm = blockIdx.y, bn = blockIdx.x;
    const int base_m = bm * 128, base_n = bn * 128;
    const int wm = (wid >> 2) * 64, wn = (wid & 3) * 32;

    const float* Ag = IS_G1 ? g_obs_tf : (g_h + (size_t)kcomp * BB * HID);
    const float* Bg = IS_G1 ? (g_W1_tf + (size_t)kcomp * DIM * HID)
                            : (g_W2_tf + (size_t)kcomp * HID * AC);

    float acc[4][4][4];
#pragma unroll
    for (int i = 0; i < 4; i++)
#pragma unroll
        for (int j = 0; j < 4; j++)
#pragma unroll
            for (int l = 0; l < 4; l++) acc[i][j][l] = 0.f;

    load_stage<NT>(0, tid, sm, smem_u32, Ag, Bg, base_m, base_n);
    load_stage<NT>(1, tid, sm, smem_u32, Ag, Bg, base_m, base_n);

    for (int s = 0; s < KSTEPS; s++) {
        if (s + 2 < KSTEPS) {
            load_stage<NT>(s + 2, tid, sm, smem_u32, Ag, Bg, base_m, base_n);
            asm volatile("cp.async.wait_group 2;" ::: "memory");
        } else if (s + 1 < KSTEPS) {
            asm volatile("cp.async.wait_group 1;" ::: "memory");
        } else {
            asm volatile("cp.async.wait_group 0;" ::: "memory");
        }
        __syncthreads();

        const float* As = sm + (s % NSTAGE) * STAGE_FLOATS;
        const float* Bs = As + A_STAGE;

#pragma unroll
        for (int k8 = 0; k8 < 4; k8++) {
            const int kb = k8 * 8;
            unsigned a[4][4];
#pragma unroll
            for (int mf = 0; mf < 4; mf++) {
                const int r0 = wm + mf * 16 + (lane >> 2);
                const int cc = kb + (lane & 3);
                a[mf][0] = __float_as_uint(As[r0 * A_STRIDE + cc]);
                a[mf][1] = __float_as_uint(As[(r0 + 8) * A_STRIDE + cc]);
                a[mf][2] = __float_as_uint(As[r0 * A_STRIDE + cc + 4]);
                a[mf][3] = __float_as_uint(As[(r0 + 8) * A_STRIDE + cc + 4]);
            }
            unsigned b[4][2];
#pragma unroll
            for (int nf = 0; nf < 4; nf++) {
                const int col = wn + nf * 8 + (lane >> 2);
                const int r0 = kb + (lane & 3);
                b[nf][0] = __float_as_uint(Bs[r0 * B_STRIDE + col]);
                b[nf][1] = __float_as_uint(Bs[(r0 + 4) * B_STRIDE + col]);
            }
#pragma unroll
            for (int mf = 0; mf < 4; mf++)
#pragma unroll
                for (int nf = 0; nf < 4; nf++) mma1688(acc[mf][nf], a[mf], b[nf]);
        }
        __syncthreads();
    }

    // ---------------- epilogue ----------------
    const float* bias = bias_all + (size_t)kcomp * NT;
    const int q = lane >> 2;

#pragma unroll
    for (int mf = 0; mf < 4; mf++) {
#pragma unroll
        for (int nf = 0; nf < 4; nf++) {
            const int col = base_n + wn + nf * 8 + (lane & 3) * 2;
            const float bv0 = bias[col], bv1 = bias[col + 1];
            acc[mf][nf][0] += bv0; acc[mf][nf][1] += bv1;
            acc[mf][nf][2] += bv0; acc[mf][nf][3] += bv1;
        }
    }

    if (IS_G1) {
        float* outp = g_h + (size_t)kcomp * BB * HID;
#pragma unroll
        for (int mf = 0; mf < 4; mf++) {
            const int row = base_m + wm + mf * 16 + q;
#pragma unroll
            for (int nf = 0; nf < 4; nf++) {
                const int col = base_n + wn + nf * 8 + (lane & 3) * 2;
                float2 p0, p1;
                p0.x = f2tf32(fmaxf(acc[mf][nf][0], 0.f));
                p0.y = f2tf32(fmaxf(acc[mf][nf][1], 0.f));
                p1.x = f2tf32(fmaxf(acc[mf][nf][2], 0.f));
                p1.y = f2tf32(fmaxf(acc[mf][nf][3], 0.f));
                *(float2*)(outp + (size_t)row * NT + col) = p0;
                *(float2*)(outp + (size_t)(row + 8) * NT + col) = p1;
            }
        }
    } else {
        float* outp = g_logits + (size_t)kcomp * BB * AC;
        const int jcol = bn * 4 + (wid & 3);   // partial-LSE column group (0..31)
#pragma unroll
        for (int mf = 0; mf < 4; mf++) {
            const int row = base_m + wm + mf * 16 + q;
#pragma unroll
            for (int nf = 0; nf < 4; nf++) {
                const int col = base_n + wn + nf * 8 + (lane & 3) * 2;
                float2 p0, p1;
                p0.x = acc[mf][nf][0]; p0.y = acc[mf][nf][1];
                p1.x = acc[mf][nf][2]; p1.y = acc[mf][nf][3];
                *(float2*)(outp + (size_t)row * NT + col) = p0;
                *(float2*)(outp + (size_t)(row + 8) * NT + col) = p1;
            }
            // fused partial logsumexp over this warp's 32 cols, rows row & row+8
            float mA = -1e30f, mB = -1e30f;
#pragma unroll
            for (int nf = 0; nf < 4; nf++) {
                mA = fmaxf(mA, fmaxf(acc[mf][nf][0], acc[mf][nf][1]));
                mB = fmaxf(mB, fmaxf(acc[mf][nf][2], acc[mf][nf][3]));
            }
            float sA = 0.f, sB = 0.f;
#pragma unroll
            for (int nf = 0; nf < 4; nf++) {
                sA += __expf(acc[mf][nf][0] - mA) + __expf(acc[mf][nf][1] - mA);
                sB += __expf(acc[mf][nf][2] - mB) + __expf(acc[mf][nf][3] - mB);
            }
#pragma unroll
            for (int o = 1; o <= 2; o <<= 1) {
                float m2 = __shfl_xor_sync(0xFFFFFFFFu, mA, o);
                float s2 = __shfl_xor_sync(0xFFFFFFFFu, sA, o);
                float nm = fmaxf(mA, m2);
                sA = sA * __expf(mA - nm) + s2 * __expf(m2 - nm);
                mA = nm;
                m2 = __shfl_xor_sync(0xFFFFFFFFu, mB, o);
                s2 = __shfl_xor_sync(0xFFFFFFFFu, sB, o);
                nm = fmaxf(mB, m2);
                sB = sB * __expf(mB - nm) + s2 * __expf(m2 - nm);
                mB = nm;
            }
            if ((lane & 3) == 0) {
                const size_t base = ((size_t)kcomp * 32 + jcol) * BB;
                g_pmax[base + row]     = mA;
                g_psum[base + row]     = sA;
                g_pmax[base + row + 8] = mB;
                g_psum[base + row + 8] = sB;
            }
        }
    }
}

// ---------------- finalize lse from 32 partials + action gather -------------
__global__ void __launch_bounds__(256) lse_final_kernel() {
    const int r = blockIdx.x * 256 + threadIdx.x;   // r = k*BB + b
    const int k = r >> 13, b = r & (BB - 1);
    float mx = -1e30f;
    float pm[32];
#pragma unroll
    for (int j = 0; j < 32; j++) {
        pm[j] = g_pmax[((size_t)k * 32 + j) * BB + b];
        mx = fmaxf(mx, pm[j]);
    }
    float s = 0.f;
#pragma unroll
    for (int j = 0; j < 32; j++)
        s += g_psum[((size_t)k * 32 + j) * BB + b] * __expf(pm[j] - mx);
    const float lse = mx + logf(s);
    g_lse[r] = lse;
    g_alp[r] = g_logits[(size_t)r * AC + g_act[b]] - lse;
}

// ---------------- per-sequence mixture recursion ----------------------------
__global__ void mix_kernel(const float* __restrict__ prior_all, float* __restrict__ out) {
    const int s = blockIdx.x;
    const int lane = threadIdx.x;
    __shared__ float sm_alp[TT * KC];

    for (int i = lane; i < TT * KC; i += 32) {
        const int t = i >> 3, k = i & 7;
        sm_alp[i] = g_alp[k * BB + s * TT + t];
    }
    __syncthreads();

    if (lane < 8) {
        const int k = lane;
        const float prior = prior_all[s * KC + k];
        float cum = 0.f;
        for (int t = 0; t < TT; t++) {
            const float m = prior + cum;
            float mx = m;
#pragma unroll
            for (int o = 4; o; o >>= 1) mx = fmaxf(mx, __shfl_xor_sync(0xFFu, mx, o));
            float se = expf(m - mx);
#pragma unroll
            for (int o = 4; o; o >>= 1) se += __shfl_xor_sync(0xFFu, se, o);
            g_mix[k * BB + s * TT + t] = m - (mx + logf(se));
            cum += sm_alp[t * 8 + k];
        }
        const float m = prior + cum;
        float mx = m;
#pragma unroll
        for (int o = 4; o; o >>= 1) mx = fmaxf(mx, __shfl_xor_sync(0xFFu, mx, o));
        float se = expf(m - mx);
#pragma unroll
        for (int o = 4; o; o >>= 1) se += __shfl_xor_sync(0xFFu, se, o);
        out[(size_t)BB * AC + s * KC + k] = m - (mx + logf(se));
    }
}

// ---------------- final combine: logsumexp over K ---------------------------
__global__ void __launch_bounds__(256) combine_kernel(float* __restrict__ out) {
    const int b = blockIdx.x;
    __shared__ float off[KC];
    if (threadIdx.x < KC) {
        const int k = threadIdx.x;
        off[k] = g_mix[k * BB + b] - g_lse[k * BB + b];
    }
    __syncthreads();

    float o[KC];
#pragma unroll
    for (int k = 0; k < KC; k++) o[k] = off[k];

#pragma unroll
    for (int i = 0; i < 4; i++) {
        const int a = threadIdx.x + i * 256;
        float v[KC];
#pragma unroll
        for (int k = 0; k < KC; k++)
            v[k] = g_logits[((size_t)k * BB + b) * AC + a] + o[k];
        float mx = v[0];
#pragma unroll
        for (int k = 1; k < KC; k++) mx = fmaxf(mx, v[k]);
        float s = 0.f;
#pragma unroll
        for (int k = 0; k < KC; k++) s += __expf(v[k] - mx);
        out[(size_t)b * AC + a] = mx + logf(s);
    }
}

// ---------------- launcher ---------------------------------------------------
extern "C" void kernel_launch(void* const* d_in, const int* in_sizes, int n_in,
                              void* d_out, int out_size) {
    const float* obs     = (const float*)d_in[0];
    const void*  actions = d_in[1];
    const float* prior   = (const float*)d_in[2];
    const float* W1      = (const float*)d_in[3];
    const float* b1      = (const float*)d_in[4];
    const float* W2      = (const float*)d_in[5];
    const float* b2      = (const float*)d_in[6];
    float* out = (float*)d_out;

    cudaFuncSetAttribute(gemm_tc<HID, true>,
                         cudaFuncAttributeMaxDynamicSharedMemorySize, SMEM_BYTES);
    cudaFuncSetAttribute(gemm_tc<AC, false>,
                         cudaFuncAttributeMaxDynamicSharedMemorySize, SMEM_BYTES);

    const int n_conv = BB * DIM + KC * DIM * HID + KC * HID * AC;
    convert_kernel<<<(n_conv + 255) / 256, 256>>>(obs, W1, W2);
    prep_actions_kernel<<<1, 1024>>>(actions);

    gemm_tc<HID, true><<<dim3(HID / 128, BB / 128, KC), 256, SMEM_BYTES>>>(b1);
    gemm_tc<AC, false><<<dim3(AC / 128, BB / 128, KC), 256, SMEM_BYTES>>>(b2);

    lse_final_kernel<<<KC * BB / 256, 256>>>();
    mix_kernel<<<SQ, 32>>>(prior, out);
    combine_kernel<<<BB, 256>>>(out);
}

// round 7
// speedup vs baseline: 1.0690x; 1.0205x over previous
#include <cuda_runtime.h>
#include <cstdint>

// Problem constants (fixed by setup_inputs)
#define KC   8
#define DIM  512
#define HID  512
#define AC   1024
#define SQ   64
#define TT   128
#define BB   8192

// ---------------- device scratch --------------------------------------------
__device__ float g_obs_tf[BB * DIM];                    //  16 MB (tf32-rounded)
__device__ float g_W1_tf[KC * DIM * HID];               //  16 MB
__device__ float g_W2_tf[KC * HID * AC];                //  32 MB
__device__ float g_h[(size_t)KC * BB * HID];            // 128 MB (tf32-rounded)
__device__ float g_logits[(size_t)KC * BB * AC];        // 256 MB
__device__ float g_pmax[KC * 32 * BB];                  //   8 MB
__device__ float g_psum[KC * 32 * BB];                  //   8 MB
__device__ float g_lse[KC * BB];
__device__ float g_alp[KC * BB];
__device__ float g_mix[KC * BB];
__device__ int   g_act[BB];

__device__ __forceinline__ float f2tf32(float x) {
    float r;
    asm("cvt.rna.tf32.f32 %0, %1;" : "=f"(r) : "f"(x));
    return r;
}

// ---------------- fp32 -> tf32 pre-rounding ---------------------------------
__global__ void convert_kernel(const float* __restrict__ obs,
                               const float* __restrict__ W1,
                               const float* __restrict__ W2) {
    int i = blockIdx.x * blockDim.x + threadIdx.x;
    const int n_obs = BB * DIM;
    const int n_w1  = KC * DIM * HID;
    const int n_w2  = KC * HID * AC;
    if (i < n_obs) { g_obs_tf[i] = f2tf32(obs[i]); return; }
    int j = i - n_obs;
    if (j < n_w1)  { g_W1_tf[j] = f2tf32(W1[j]); return; }
    int l = j - n_w1;
    if (l < n_w2)  { g_W2_tf[l] = f2tf32(W2[l]); }
}

// ---------------- actions: detect int32 vs int64, normalize to int32 --------
__global__ void prep_actions_kernel(const void* __restrict__ act) {
    const unsigned long long* p64 = (const unsigned long long*)act;
    int bad = 0;
    for (int i = threadIdx.x; i < BB / 2; i += blockDim.x)
        if (p64[i] > 0xFFFFFFFFull) bad = 1;
    int is32 = __syncthreads_or(bad);
    if (is32) {
        const int* p32 = (const int*)act;
        for (int i = threadIdx.x; i < BB; i += blockDim.x) g_act[i] = p32[i];
    } else {
        const long long* pl = (const long long*)act;
        for (int i = threadIdx.x; i < BB; i += blockDim.x) g_act[i] = (int)pl[i];
    }
}

// ---------------- tf32 mma.sync m16n8k8 -------------------------------------
__device__ __forceinline__ void mma1688(float* c, const unsigned* a, const unsigned* b) {
    asm volatile(
        "mma.sync.aligned.m16n8k8.row.col.f32.tf32.tf32.f32 "
        "{%0,%1,%2,%3}, {%4,%5,%6,%7}, {%8,%9}, {%0,%1,%2,%3};\n"
        : "+f"(c[0]), "+f"(c[1]), "+f"(c[2]), "+f"(c[3])
        : "r"(a[0]), "r"(a[1]), "r"(a[2]), "r"(a[3]), "r"(b[0]), "r"(b[1]));
}

#define LDSM_X4(r0, r1, r2, r3, addr) \
    asm volatile("ldmatrix.sync.aligned.m8n8.x4.shared.b16 {%0,%1,%2,%3}, [%4];" \
                 : "=r"(r0), "=r"(r1), "=r"(r2), "=r"(r3) : "r"(addr))

#define CPASYNC16(dst, src) \
    asm volatile("cp.async.ca.shared.global [%0], [%1], 16;" :: "r"(dst), "l"(src))
#define CP_COMMIT() asm volatile("cp.async.commit_group;" ::: "memory")

// ---------------- GEMM: C[8192, NT] = A[8192,512] * B[512,NT] ---------------
// CTA tile 128x128, 256 thr = 8 warps (2m x 4n), warp 64x32.
// A: swizzled K-major tile (128 rows x 128B), fragments via ldmatrix.x4.
// B: round-4 natural [k][n] padded tile, scalar LDS fragments.
#define NSTAGE     3
#define KSTEPS     16
#define A_TILE_B   16384                     // 128 * 128 B
#define B_STRIDE   136
#define B_TILE_F   (32 * B_STRIDE)           // 4352 floats = 17408 B
#define B_BASE_B   (NSTAGE * A_TILE_B)       // 49152
#define SMEM_BYTES (B_BASE_B + NSTAGE * B_TILE_F * 4)  // 101376 B

template <int NT>
__device__ __forceinline__ void load_stage(int s, int tid, uint32_t smem_u32,
                                           const float* Ag, const float* Bg,
                                           int base_m, int base_n) {
    const int buf = s % NSTAGE;
    const uint32_t abase = smem_u32 + buf * A_TILE_B;
    const uint32_t bbase = smem_u32 + B_BASE_B + buf * (B_TILE_F * 4);
    const int kofs = s * 32;
#pragma unroll
    for (int i = 0; i < 4; i++) {
        const int idx = tid + 256 * i;                 // 0..1023
        // A: 128 rows x 8 16B-chunks, XOR-16B swizzle
        const int row = idx >> 3, kc = idx & 7;
        const uint32_t doff = (uint32_t)(row * 128 + ((kc * 16) ^ ((row & 7) << 4)));
        CPASYNC16(abase + doff, Ag + (size_t)(base_m + row) * 512 + kofs + kc * 4);
        // B: 32 k-rows x 128 n-cols, padded stride
        const int kr = idx >> 5, nq = (idx & 31) * 4;
        CPASYNC16(bbase + (uint32_t)((kr * B_STRIDE + nq) * 4),
                  Bg + (size_t)(kofs + kr) * NT + base_n + nq);
    }
    CP_COMMIT();
}

template <int NT, bool IS_G1>
__global__ void __launch_bounds__(256, 2) gemm_tc(const float* __restrict__ bias_all) {
    extern __shared__ float sm[];
    const uint32_t smem_u32 = (uint32_t)__cvta_generic_to_shared(sm);
    const int tid = threadIdx.x, wid = tid >> 5, lane = tid & 31;
    const int kcomp = blockIdx.z, bm = blockIdx.y, bn = blockIdx.x;
    const int base_m = bm * 128, base_n = bn * 128;
    const int wm = (wid >> 2) * 64, wn = (wid & 3) * 32;

    const float* Ag = IS_G1 ? g_obs_tf : (g_h + (size_t)kcomp * BB * HID);
    const float* Bg = IS_G1 ? (g_W1_tf + (size_t)kcomp * DIM * HID)
                            : (g_W2_tf + (size_t)kcomp * HID * AC);

    float acc[4][4][4];
#pragma unroll
    for (int i = 0; i < 4; i++)
#pragma unroll
        for (int j = 0; j < 4; j++)
#pragma unroll
            for (int l = 0; l < 4; l++) acc[i][j][l] = 0.f;

    // A ldmatrix base addresses (k8 = 0); per-k8 address = base ^ (k8*32).
    // x4 matrices: [m0-7,k0-3][m8-15,k0-3][m0-7,k4-7][m8-15,k4-7]
    const int a_hi = (lane >> 4) & 1;     // k+4 chunk
    const int a_r8 = (lane >> 3) & 1;     // +8 row half
    uint32_t a_base[4];
#pragma unroll
    for (int mf = 0; mf < 4; mf++) {
        const int row = wm + mf * 16 + a_r8 * 8 + (lane & 7);
        a_base[mf] = (uint32_t)(row * 128 + ((a_hi * 16) ^ ((row & 7) << 4)));
    }

    load_stage<NT>(0, tid, smem_u32, Ag, Bg, base_m, base_n);
    load_stage<NT>(1, tid, smem_u32, Ag, Bg, base_m, base_n);

    for (int s = 0; s < KSTEPS; s++) {
        if (s + 2 < KSTEPS) {
            load_stage<NT>(s + 2, tid, smem_u32, Ag, Bg, base_m, base_n);
            asm volatile("cp.async.wait_group 2;" ::: "memory");
        } else if (s + 1 < KSTEPS) {
            asm volatile("cp.async.wait_group 1;" ::: "memory");
        } else {
            asm volatile("cp.async.wait_group 0;" ::: "memory");
        }
        __syncthreads();

        const uint32_t As = smem_u32 + (s % NSTAGE) * A_TILE_B;
        const float* Bs = sm + (B_BASE_B / 4) + (s % NSTAGE) * B_TILE_F;

#pragma unroll
        for (int k8 = 0; k8 < 4; k8++) {
            const uint32_t kx = (uint32_t)(k8 * 32);
            const int kb = k8 * 8;
            unsigned a[4][4], b[4][2];
#pragma unroll
            for (int mf = 0; mf < 4; mf++)
                LDSM_X4(a[mf][0], a[mf][1], a[mf][2], a[mf][3], As + (a_base[mf] ^ kx));
#pragma unroll
            for (int nf = 0; nf < 4; nf++) {
                const int col = wn + nf * 8 + (lane >> 2);
                const int r0 = kb + (lane & 3);
                b[nf][0] = __float_as_uint(Bs[r0 * B_STRIDE + col]);
                b[nf][1] = __float_as_uint(Bs[(r0 + 4) * B_STRIDE + col]);
            }
#pragma unroll
            for (int mf = 0; mf < 4; mf++)
#pragma unroll
                for (int nf = 0; nf < 4; nf++) mma1688(acc[mf][nf], a[mf], b[nf]);
        }
        __syncthreads();
    }

    // ---------------- epilogue ----------------
    const float* bias = bias_all + (size_t)kcomp * NT;
    const int q = lane >> 2;

#pragma unroll
    for (int mf = 0; mf < 4; mf++) {
#pragma unroll
        for (int nf = 0; nf < 4; nf++) {
            const int col = base_n + wn + nf * 8 + (lane & 3) * 2;
            const float bv0 = bias[col], bv1 = bias[col + 1];
            acc[mf][nf][0] += bv0; acc[mf][nf][1] += bv1;
            acc[mf][nf][2] += bv0; acc[mf][nf][3] += bv1;
        }
    }

    if (IS_G1) {
        float* outp = g_h + (size_t)kcomp * BB * HID;
#pragma unroll
        for (int mf = 0; mf < 4; mf++) {
            const int row = base_m + wm + mf * 16 + q;
#pragma unroll
            for (int nf = 0; nf < 4; nf++) {
                const int col = base_n + wn + nf * 8 + (lane & 3) * 2;
                float2 p0, p1;
                p0.x = f2tf32(fmaxf(acc[mf][nf][0], 0.f));
                p0.y = f2tf32(fmaxf(acc[mf][nf][1], 0.f));
                p1.x = f2tf32(fmaxf(acc[mf][nf][2], 0.f));
                p1.y = f2tf32(fmaxf(acc[mf][nf][3], 0.f));
                *(float2*)(outp + (size_t)row * NT + col) = p0;
                *(float2*)(outp + (size_t)(row + 8) * NT + col) = p1;
            }
        }
    } else {
        float* outp = g_logits + (size_t)kcomp * BB * AC;
        const int jcol = bn * 4 + (wid & 3);   // partial-LSE column group (0..31)
#pragma unroll
        for (int mf = 0; mf < 4; mf++) {
            const int row = base_m + wm + mf * 16 + q;
#pragma unroll
            for (int nf = 0; nf < 4; nf++) {
                const int col = base_n + wn + nf * 8 + (lane & 3) * 2;
                float2 p0, p1;
                p0.x = acc[mf][nf][0]; p0.y = acc[mf][nf][1];
                p1.x = acc[mf][nf][2]; p1.y = acc[mf][nf][3];
                *(float2*)(outp + (size_t)row * NT + col) = p0;
                *(float2*)(outp + (size_t)(row + 8) * NT + col) = p1;
            }
            // fused partial logsumexp over this warp's 32 cols, rows row & row+8
            float mA = -1e30f, mB = -1e30f;
#pragma unroll
            for (int nf = 0; nf < 4; nf++) {
                mA = fmaxf(mA, fmaxf(acc[mf][nf][0], acc[mf][nf][1]));
                mB = fmaxf(mB, fmaxf(acc[mf][nf][2], acc[mf][nf][3]));
            }
            float sA = 0.f, sB = 0.f;
#pragma unroll
            for (int nf = 0; nf < 4; nf++) {
                sA += __expf(acc[mf][nf][0] - mA) + __expf(acc[mf][nf][1] - mA);
                sB += __expf(acc[mf][nf][2] - mB) + __expf(acc[mf][nf][3] - mB);
            }
#pragma unroll
            for (int o = 1; o <= 2; o <<= 1) {
                float m2 = __shfl_xor_sync(0xFFFFFFFFu, mA, o);
                float s2 = __shfl_xor_sync(0xFFFFFFFFu, sA, o);
                float nm = fmaxf(mA, m2);
                sA = sA * __expf(mA - nm) + s2 * __expf(m2 - nm);
                mA = nm;
                m2 = __shfl_xor_sync(0xFFFFFFFFu, mB, o);
                s2 = __shfl_xor_sync(0xFFFFFFFFu, sB, o);
                nm = fmaxf(mB, m2);
                sB = sB * __expf(mB - nm) + s2 * __expf(m2 - nm);
                mB = nm;
            }
            if ((lane & 3) == 0) {
                const size_t base = ((size_t)kcomp * 32 + jcol) * BB;
                g_pmax[base + row]     = mA;
                g_psum[base + row]     = sA;
                g_pmax[base + row + 8] = mB;
                g_psum[base + row + 8] = sB;
            }
        }
    }
}

// ---------------- finalize lse from 32 partials + action gather -------------
__global__ void __launch_bounds__(256) lse_final_kernel() {
    const int r = blockIdx.x * 256 + threadIdx.x;   // r = k*BB + b
    const int k = r >> 13, b = r & (BB - 1);
    float mx = -1e30f;
    float pm[32];
#pragma unroll
    for (int j = 0; j < 32; j++) {
        pm[j] = g_pmax[((size_t)k * 32 + j) * BB + b];
        mx = fmaxf(mx, pm[j]);
    }
    float s = 0.f;
#pragma unroll
    for (int j = 0; j < 32; j++)
        s += g_psum[((size_t)k * 32 + j) * BB + b] * __expf(pm[j] - mx);
    const float lse = mx + logf(s);
    g_lse[r] = lse;
    g_alp[r] = g_logits[(size_t)r * AC + g_act[b]] - lse;
}

// ---------------- per-sequence mixture recursion ----------------------------
__global__ void mix_kernel(const float* __restrict__ prior_all, float* __restrict__ out) {
    const int s = blockIdx.x;
    const int lane = threadIdx.x;
    __shared__ float sm_alp[TT * KC];

    for (int i = lane; i < TT * KC; i += 32) {
        const int t = i >> 3, k = i & 7;
        sm_alp[i] = g_alp[k * BB + s * TT + t];
    }
    __syncthreads();

    if (lane < 8) {
        const int k = lane;
        const float prior = prior_all[s * KC + k];
        float cum = 0.f;
        for (int t = 0; t < TT; t++) {
            const float m = prior + cum;
            float mx = m;
#pragma unroll
            for (int o = 4; o; o >>= 1) mx = fmaxf(mx, __shfl_xor_sync(0xFFu, mx, o));
            float se = expf(m - mx);
#pragma unroll
            for (int o = 4; o; o >>= 1) se += __shfl_xor_sync(0xFFu, se, o);
            g_mix[k * BB + s * TT + t] = m - (mx + logf(se));
            cum += sm_alp[t * 8 + k];
        }
        const float m = prior + cum;
        float mx = m;
#pragma unroll
        for (int o = 4; o; o >>= 1) mx = fmaxf(mx, __shfl_xor_sync(0xFFu, mx, o));
        float se = expf(m - mx);
#pragma unroll
        for (int o = 4; o; o >>= 1) se += __shfl_xor_sync(0xFFu, se, o);
        out[(size_t)BB * AC + s * KC + k] = m - (mx + logf(se));
    }
}

// ---------------- final combine: logsumexp over K ---------------------------
__global__ void __launch_bounds__(256) combine_kernel(float* __restrict__ out) {
    const int b = blockIdx.x;
    __shared__ float off[KC];
    if (threadIdx.x < KC) {
        const int k = threadIdx.x;
        off[k] = g_mix[k * BB + b] - g_lse[k * BB + b];
    }
    __syncthreads();

    float o[KC];
#pragma unroll
    for (int k = 0; k < KC; k++) o[k] = off[k];

#pragma unroll
    for (int i = 0; i < 4; i++) {
        const int a = threadIdx.x + i * 256;
        float v[KC];
#pragma unroll
        for (int k = 0; k < KC; k++)
            v[k] = g_logits[((size_t)k * BB + b) * AC + a] + o[k];
        float mx = v[0];
#pragma unroll
        for (int k = 1; k < KC; k++) mx = fmaxf(mx, v[k]);
        float s = 0.f;
#pragma unroll
        for (int k = 0; k < KC; k++) s += __expf(v[k] - mx);
        out[(size_t)b * AC + a] = mx + logf(s);
    }
}

// ---------------- launcher ---------------------------------------------------
extern "C" void kernel_launch(void* const* d_in, const int* in_sizes, int n_in,
                              void* d_out, int out_size) {
    const float* obs     = (const float*)d_in[0];
    const void*  actions = d_in[1];
    const float* prior   = (const float*)d_in[2];
    const float* W1      = (const float*)d_in[3];
    const float* b1      = (const float*)d_in[4];
    const float* W2      = (const float*)d_in[5];
    const float* b2      = (const float*)d_in[6];
    float* out = (float*)d_out;

    cudaFuncSetAttribute(gemm_tc<HID, true>,
                         cudaFuncAttributeMaxDynamicSharedMemorySize, SMEM_BYTES);
    cudaFuncSetAttribute(gemm_tc<AC, false>,
                         cudaFuncAttributeMaxDynamicSharedMemorySize, SMEM_BYTES);

    const int n_conv = BB * DIM + KC * DIM * HID + KC * HID * AC;
    convert_kernel<<<(n_conv + 255) / 256, 256>>>(obs, W1, W2);
    prep_actions_kernel<<<1, 1024>>>(actions);

    gemm_tc<HID, true><<<dim3(HID / 128, BB / 128, KC), 256, SMEM_BYTES>>>(b1);
    gemm_tc<AC, false><<<dim3(AC / 128, BB / 128, KC), 256, SMEM_BYTES>>>(b2);

    lse_final_kernel<<<KC * BB / 256, 256>>>();
    mix_kernel<<<SQ, 32>>>(prior, out);
    combine_kernel<<<BB, 256>>>(out);
}